// round 7
// baseline (speedup 1.0000x reference)
#include <cuda_runtime.h>

#define B 16
#define G 5000
#define K 256
#define HID 64
#define STEPS 10
#define NCHUNK 160
#define NG1 32            // genes/block in K1 (160*32 = 5120 >= 5000)
#define GT 32             // genes/block in K3 (157 blocks)
#define CLS 8             // cluster size for K2

// Scratch (no allocations; monotone/idempotent or overwritten => replay-safe)
__device__ unsigned g_tmodU[B * K];      // atomicMax(float-as-uint), idempotent
__device__ __align__(16) float g_Z[B][K];
__device__ float g_coff[B];

#define FMAXUPD(ACC, T, MV)                         \
    ACC.x = fmaxf(ACC.x, (T) * MV.x);               \
    ACC.y = fmaxf(ACC.y, (T) * MV.y);               \
    ACC.z = fmaxf(ACC.z, (T) * MV.z);               \
    ACC.w = fmaxf(ACC.w, (T) * MV.w);

// ---------------------------------------------------------------------------
// K1: max-pool. 160 blocks x 1024 threads. Thread (q4, h, ge): b-quad h,
// k-quad q4, 8 genes. Block partials reduced in smem, merged across blocks
// via atomicMax on float-as-uint (products >= 0 -> bit-monotone; idempotent).
// ---------------------------------------------------------------------------
__global__ __launch_bounds__(1024) void k1_maxpool(
    const float* __restrict__ t, const float* __restrict__ M)
{
    extern __shared__ float s1[];
    float*  ts   = s1;                    // [B][NG1] = 512
    float4* red4 = (float4*)(s1 + 512);   // [64][64] float4 = 64 KB

    const int tid = threadIdx.x;
    const int g0  = blockIdx.x * NG1;

    for (int i = tid; i < B * NG1; i += 1024) {
        int g = g0 + (i & 31);
        ts[i] = (g < G) ? t[(i >> 5) * G + g] : 0.0f;
    }
    __syncthreads();

    const int q4 = tid & 63;
    const int h  = (tid >> 6) & 3;
    const int ge = tid >> 8;

    float4 acc[4];
#pragma unroll
    for (int ii = 0; ii < 4; ii++) acc[ii] = make_float4(0.f, 0.f, 0.f, 0.f);

#pragma unroll
    for (int i0 = 0; i0 < 8; i0 += 4) {
        float4 mv[4];
#pragma unroll
        for (int u = 0; u < 4; u++) {
            int gl = ge + 4 * (i0 + u);
            int g  = g0 + gl;
            mv[u] = (g < G) ? *(const float4*)(M + (size_t)g * K + 4 * q4)
                            : make_float4(0.f, 0.f, 0.f, 0.f);
        }
#pragma unroll
        for (int u = 0; u < 4; u++) {
            int gl = ge + 4 * (i0 + u);
            float4 m = mv[u];
#pragma unroll
            for (int ii = 0; ii < 4; ii++) {
                float tv = ts[(4 * h + ii) * NG1 + gl];
                FMAXUPD(acc[ii], tv, m)
            }
        }
    }

#pragma unroll
    for (int ii = 0; ii < 4; ii++)
        red4[(((ge * 4 + h) * 4 + ii) << 6) + q4] = acc[ii];
    __syncthreads();

    if (tid < 256) {
        int q4r = tid & 63, hr = tid >> 6;
#pragma unroll
        for (int ii = 0; ii < 4; ii++) {
            float4 a = red4[(((0 * 4 + hr) * 4 + ii) << 6) + q4r];
            float4 c = red4[(((1 * 4 + hr) * 4 + ii) << 6) + q4r];
            float4 d = red4[(((2 * 4 + hr) * 4 + ii) << 6) + q4r];
            float4 e = red4[(((3 * 4 + hr) * 4 + ii) << 6) + q4r];
            float4 r;
            r.x = fmaxf(fmaxf(a.x, c.x), fmaxf(d.x, e.x));
            r.y = fmaxf(fmaxf(a.y, c.y), fmaxf(d.y, e.y));
            r.z = fmaxf(fmaxf(a.z, c.z), fmaxf(d.z, e.z));
            r.w = fmaxf(fmaxf(a.w, c.w), fmaxf(d.w, e.w));
            int bb = 4 * hr + ii;
            unsigned* dst = &g_tmodU[bb * K + 4 * q4r];
            atomicMax(dst + 0, __float_as_uint(r.x));
            atomicMax(dst + 1, __float_as_uint(r.y));
            atomicMax(dst + 2, __float_as_uint(r.z));
            atomicMax(dst + 3, __float_as_uint(r.w));
        }
    }
}
#define K1_SMEM ((512 + 64 * 64 * 4) * (int)sizeof(float))

// ---------------------------------------------------------------------------
// K2: APPNP on clusters. 128 blocks = 16 clusters of 8; cluster c handles
// batch row b = blockIdx/8. CTA rank r owns k in [32r, 32r+32).
// Warp w = local k (global kg = 32r + w); lane l owns j in {l+32u, u=0..7},
// A column slice entirely in registers. Per step: 8 LDS + 8 FMA + warp
// shuffle-reduce; lane0 multicasts z_new to all 8 CTAs' next Z buffer via
// st.shared::cluster; cluster.sync per step. Double-buffered Z.
// ---------------------------------------------------------------------------
__global__ __launch_bounds__(1024, 1) __cluster_dims__(CLS, 1, 1)
void k2_appnp(
    const float* __restrict__ A,
    const int*   __restrict__ cell_idx,
    const float* __restrict__ cell_emb,
    const float* __restrict__ W2,
    const float* __restrict__ b2)
{
    __shared__ float Zbuf[2][K];

    const int tid = threadIdx.x;
    const int b   = blockIdx.x >> 3;
    const int w   = tid >> 5;
    const int l   = tid & 31;

    unsigned r;
    asm("mov.u32 %0, %%cluster_ctarank;" : "=r"(r));
    const int kg = 32 * (int)r + w;

    // cell offset: rank 0, warp 0
    if (r == 0 && w == 0) {
        int ci = cell_idx[b];
        float v = cell_emb[ci * HID + l] * W2[l]
                + cell_emb[ci * HID + 32 + l] * W2[32 + l];
#pragma unroll
        for (int o = 16; o > 0; o >>= 1)
            v += __shfl_down_sync(0xffffffffu, v, o);
        if (l == 0) g_coff[b] = v + b2[0];
    }

    // A column slice in registers: regA[u] = A[l+32u][kg]
    float regA[8];
#pragma unroll
    for (int u = 0; u < 8; u++)
        regA[u] = A[(l + 32 * u) * K + kg];

    const float s_k = __uint_as_float(g_tmodU[b * K + kg]);
    if (tid < K) Zbuf[0][tid] = __uint_as_float(g_tmodU[b * K + tid]);
    __syncthreads();

    int cur = 0;
#pragma unroll 1
    for (int s = 0; s < STEPS; s++) {
        float acc = 0.f;
#pragma unroll
        for (int u = 0; u < 8; u++)
            acc = fmaf(regA[u], Zbuf[cur][l + 32 * u], acc);
#pragma unroll
        for (int o = 16; o > 0; o >>= 1)
            acc += __shfl_down_sync(0xffffffffu, acc, o);

        const int nxt = cur ^ 1;
        if (l == 0) {
            float zn = 0.9f * acc + 0.1f * s_k;
            unsigned laddr = (unsigned)__cvta_generic_to_shared(&Zbuf[nxt][kg]);
#pragma unroll
            for (int pr = 0; pr < CLS; pr++) {
                unsigned raddr;
                asm volatile("mapa.shared::cluster.u32 %0, %1, %2;"
                             : "=r"(raddr) : "r"(laddr), "r"(pr));
                asm volatile("st.shared::cluster.f32 [%0], %1;"
                             :: "r"(raddr), "f"(zn) : "memory");
            }
        }
        asm volatile("barrier.cluster.arrive.aligned;" ::: "memory");
        asm volatile("barrier.cluster.wait.aligned;" ::: "memory");
        cur = nxt;
    }

    if (l == 0)
        g_Z[b][kg] = Zbuf[cur][kg];
}

// ---------------------------------------------------------------------------
// K3: z_gene + MLP + out. 157 blocks x 1024 threads, 32 genes/block.
// ---------------------------------------------------------------------------
__global__ __launch_bounds__(1024) void k3_out(
    const float* __restrict__ ctl,
    const float* __restrict__ t,
    const float* __restrict__ M,
    const float* __restrict__ W1,
    const float* __restrict__ b1,
    const float* __restrict__ W2,
    float* __restrict__ out)
{
    extern __shared__ float s3[];
    float*  Ms    = s3;                          // 32*257 = 8224
    float2* Zp    = (float2*)(s3 + 8224);        // [K][8]
    float2* zpart = (float2*)(s3 + 8224 + 4096); // [4][256]
    float*  W1s   = s3 + 8224 + 4096 + 2048;     // 192
    float*  b1s   = W1s + 192;
    float*  W2s   = b1s + HID;
    float*  coffs = W2s + HID;                   // 16

    const int tid = threadIdx.x;
    const int g0  = blockIdx.x * GT;

    for (int i = tid; i < GT * 64; i += 1024) {
        int gl = i >> 6, jq = i & 63;
        int g = g0 + gl;
        float4 v = (g < G) ? *(const float4*)(M + (size_t)g * K + 4 * jq)
                           : make_float4(0.f, 0.f, 0.f, 0.f);
        float* d = Ms + gl * 257 + 4 * jq;
        d[0] = v.x; d[1] = v.y; d[2] = v.z; d[3] = v.w;
    }
    for (int i = tid; i < K * 8; i += 1024) {
        int j = i >> 3, p = i & 7;
        Zp[i] = make_float2(g_Z[p][j], g_Z[p + 8][j]);
    }
    if (tid < 3 * HID) W1s[tid] = W1[tid];
    if (tid < HID) { b1s[tid] = b1[tid]; W2s[tid] = W2[tid]; }
    if (tid < B)   coffs[tid] = g_coff[tid];
    __syncthreads();

    {
        const int jh = tid >> 8;
        const int rr = tid & 255;
        const int p  = rr & 7;
        const int gl = rr >> 3;
        const int j0 = jh * 64;
        float z0 = 0.f, z1 = 0.f;
        const float*  Mrow = Ms + gl * 257;
        const float2* Zw   = Zp + p;
#pragma unroll 8
        for (int j = j0; j < j0 + 64; j++) {
            float  m  = Mrow[j];
            float2 zz = Zw[j * 8];
            z0 = fmaf(zz.x, m, z0);
            z1 = fmaf(zz.y, m, z1);
        }
        zpart[jh * 256 + rr] = make_float2(z0, z1);
    }
    __syncthreads();

    if (tid < 256) {
        int p = tid & 7, gl = tid >> 3;
        int g = g0 + gl;
        if (g < G) {
            float2 pa = zpart[tid],       pb = zpart[256 + tid];
            float2 pc = zpart[512 + tid], pd = zpart[768 + tid];
            float z0 = pa.x + pb.x + pc.x + pd.x;
            float z1 = pa.y + pb.y + pc.y + pd.y;
            float c0 = ctl[p * G + g], c1v = ctl[(p + 8) * G + g];
            float t0 = t[p * G + g],   t1v = t[(p + 8) * G + g];
            float y0 = coffs[p], y1 = coffs[p + 8];
#pragma unroll 8
            for (int j = 0; j < HID; j++) {
                float w1c = W1s[j], w1t = W1s[HID + j], w1z = W1s[2 * HID + j];
                float bbv = b1s[j], w2 = W2s[j];
                float v0 = fmaf(c0, w1c, fmaf(t0, w1t, fmaf(z0, w1z, bbv)));
                float v1 = fmaf(c1v, w1c, fmaf(t1v, w1t, fmaf(z1, w1z, bbv)));
                y0 = fmaf(fmaxf(v0, 0.f), w2, y0);
                y1 = fmaf(fmaxf(v1, 0.f), w2, y1);
            }
            out[p * G + g]       = y0;
            out[(p + 8) * G + g] = y1;
        }
    }
}
#define K3_SMEM ((8224 + 4096 + 2048 + 192 + HID + HID + B) * (int)sizeof(float))

// ---------------------------------------------------------------------------
// metadata order: ctl, drug_targets, cell_idx, drug_fp, M, A, W1, b1,
//                 cell_emb, W2, b2   -> output [B, G] float32
// ---------------------------------------------------------------------------
extern "C" void kernel_launch(void* const* d_in, const int* in_sizes, int n_in,
                              void* d_out, int out_size)
{
    const float* ctl      = (const float*)d_in[0];
    const float* tgt      = (const float*)d_in[1];
    const int*   cell_idx = (const int*)  d_in[2];
    // d_in[3] = drug_fp (unused by the model)
    const float* M        = (const float*)d_in[4];
    const float* A        = (const float*)d_in[5];
    const float* W1       = (const float*)d_in[6];
    const float* b1       = (const float*)d_in[7];
    const float* cell_emb = (const float*)d_in[8];
    const float* W2       = (const float*)d_in[9];
    const float* b2       = (const float*)d_in[10];
    float* out = (float*)d_out;

    cudaFuncSetAttribute(k1_maxpool,
                         cudaFuncAttributeMaxDynamicSharedMemorySize, K1_SMEM);
    cudaFuncSetAttribute(k3_out,
                         cudaFuncAttributeMaxDynamicSharedMemorySize, K3_SMEM);

    k1_maxpool<<<NCHUNK, 1024, K1_SMEM>>>(tgt, M);
    k2_appnp<<<B * CLS, 1024>>>(A, cell_idx, cell_emb, W2, b2);
    k3_out<<<(G + GT - 1) / GT, 1024, K3_SMEM>>>(ctl, tgt, M, W1, b1, W2, out);
}

// round 8
// speedup vs baseline: 1.4167x; 1.4167x over previous
#include <cuda_runtime.h>

#define B 16
#define G 5000
#define K 256
#define HID 64
#define STEPS 10
#define NCHUNK 160
#define NG1 32            // genes/block in K1 (160*32 = 5120 >= 5000)
#define GT 32             // genes/block in K3 (157 blocks)

typedef unsigned long long u64;

// Scratch (no allocations allowed)
__device__ __align__(16) float g_partial[NCHUNK][B][K];  // 2.6 MB
__device__ __align__(16) float g_Z[B][K];
__device__ float g_coff[B];

// ---- packed fp32x2 helpers (FFMA2 is PTX-only) ----
__device__ __forceinline__ u64 pack2(float x, float y) {
    u64 r; asm("mov.b64 %0, {%1, %2};" : "=l"(r) : "f"(x), "f"(y)); return r;
}
__device__ __forceinline__ void unpack2(u64 v, float& x, float& y) {
    asm("mov.b64 {%0, %1}, %2;" : "=f"(x), "=f"(y) : "l"(v));
}
__device__ __forceinline__ void ffma2(u64& acc, u64 a, u64 b) {
    asm("fma.rn.f32x2 %0, %1, %2, %0;" : "+l"(acc) : "l"(a), "l"(b));
}
__device__ __forceinline__ u64 lds_b64(unsigned a) {
    u64 r; asm volatile("ld.shared.b64 %0, [%1];" : "=l"(r) : "r"(a)); return r;
}
__device__ __forceinline__ void lds_v2b64(unsigned a, u64& x, u64& y) {
    asm volatile("ld.shared.v2.b64 {%0, %1}, [%2];" : "=l"(x), "=l"(y) : "r"(a));
}
__device__ __forceinline__ void sts_b64(unsigned a, u64 v) {
    asm volatile("st.shared.b64 [%0], %1;" :: "r"(a), "l"(v) : "memory");
}

#define FMAXUPD(ACC, T, MV)                         \
    ACC.x = fmaxf(ACC.x, (T) * MV.x);               \
    ACC.y = fmaxf(ACC.y, (T) * MV.y);               \
    ACC.z = fmaxf(ACC.z, (T) * MV.z);               \
    ACC.w = fmaxf(ACC.w, (T) * MV.w);

// ---------------------------------------------------------------------------
// K1: max-pool (R6 verbatim). 160 blocks x 1024 threads.
// ---------------------------------------------------------------------------
__global__ __launch_bounds__(1024) void k1_maxpool(
    const float* __restrict__ t, const float* __restrict__ M)
{
    extern __shared__ float s1[];
    float*  ts   = s1;                    // [B][NG1] = 512
    float4* red4 = (float4*)(s1 + 512);   // [64][64] float4 = 64 KB

    const int tid = threadIdx.x;
    const int g0  = blockIdx.x * NG1;

    for (int i = tid; i < B * NG1; i += 1024) {
        int g = g0 + (i & 31);
        ts[i] = (g < G) ? t[(i >> 5) * G + g] : 0.0f;
    }
    __syncthreads();

    const int q4 = tid & 63;
    const int h  = (tid >> 6) & 3;
    const int ge = tid >> 8;

    float4 acc[4];
#pragma unroll
    for (int ii = 0; ii < 4; ii++) acc[ii] = make_float4(0.f, 0.f, 0.f, 0.f);

#pragma unroll
    for (int i0 = 0; i0 < 8; i0 += 4) {
        float4 mv[4];
#pragma unroll
        for (int u = 0; u < 4; u++) {
            int gl = ge + 4 * (i0 + u);
            int g  = g0 + gl;
            mv[u] = (g < G) ? *(const float4*)(M + (size_t)g * K + 4 * q4)
                            : make_float4(0.f, 0.f, 0.f, 0.f);
        }
#pragma unroll
        for (int u = 0; u < 4; u++) {
            int gl = ge + 4 * (i0 + u);
            float4 m = mv[u];
#pragma unroll
            for (int ii = 0; ii < 4; ii++) {
                float tv = ts[(4 * h + ii) * NG1 + gl];
                FMAXUPD(acc[ii], tv, m)
            }
        }
    }

#pragma unroll
    for (int ii = 0; ii < 4; ii++)
        red4[(((ge * 4 + h) * 4 + ii) << 6) + q4] = acc[ii];
    __syncthreads();

    if (tid < 256) {
        int q4r = tid & 63, hr = tid >> 6;
#pragma unroll
        for (int ii = 0; ii < 4; ii++) {
            float4 a = red4[(((0 * 4 + hr) * 4 + ii) << 6) + q4r];
            float4 c = red4[(((1 * 4 + hr) * 4 + ii) << 6) + q4r];
            float4 d = red4[(((2 * 4 + hr) * 4 + ii) << 6) + q4r];
            float4 e = red4[(((3 * 4 + hr) * 4 + ii) << 6) + q4r];
            float4 r;
            r.x = fmaxf(fmaxf(a.x, c.x), fmaxf(d.x, e.x));
            r.y = fmaxf(fmaxf(a.y, c.y), fmaxf(d.y, e.y));
            r.z = fmaxf(fmaxf(a.z, c.z), fmaxf(d.z, e.z));
            r.w = fmaxf(fmaxf(a.w, c.w), fmaxf(d.w, e.w));
            *(float4*)(&g_partial[blockIdx.x][4 * hr + ii][4 * q4r]) = r;
        }
    }
}
#define K1_SMEM ((512 + 64 * 64 * 4) * (int)sizeof(float))

// ---------------------------------------------------------------------------
// K2: APPNP with packed fp32x2 FMA. 16 blocks x 1024 threads.
// Thread (q = tid>>8, k = tid&255) owns j in [64q, 64q+64) as 32 j-pairs:
// pairs 0..11 in smem (pre-packed b64), pairs 12..31 in registers (40 regs).
// smem byte layout: Asm2 [48 rows][256] u64 = 98304B | Zs 1024B | pred 4096B
// ---------------------------------------------------------------------------
#define K2_ASM_BYTES (48 * 256 * 8)
#define K2_SMEM_BYTES (K2_ASM_BYTES + 1024 + 4096)

__global__ __launch_bounds__(1024, 1) void k2_appnp(
    const float* __restrict__ A,
    const int*   __restrict__ cell_idx,
    const float* __restrict__ cell_emb,
    const float* __restrict__ W2,
    const float* __restrict__ b2)
{
    extern __shared__ float sm[];
    float* Zs   = sm + K2_ASM_BYTES / 4;           // 256 floats
    float* pred = Zs + 256;                         // 1024 floats
    const unsigned abase = (unsigned)__cvta_generic_to_shared(sm);
    const unsigned zbase = abase + K2_ASM_BYTES;

    const int tid = threadIdx.x;
    const int b   = blockIdx.x;
    const int q   = tid >> 8;
    const int k   = tid & 255;

    // --- register A pairs: j in [64q+24, 64q+64), coalesced LDG ---
    u64 regA2[20];
#pragma unroll
    for (int u = 0; u < 20; u++) {
        int j0 = 64 * q + 24 + 2 * u;
        regA2[u] = pack2(A[j0 * K + k], A[(j0 + 1) * K + k]);
    }

    // --- smem A pairs: rows r = q*12 + jp hold (A[64q+2jp], A[64q+2jp+1]) ---
    for (int i = tid; i < 48 * 256; i += 1024) {
        int r = i >> 8, kk = i & 255;
        int jq = r / 12, jj = r - 12 * jq;
        int j0 = 64 * jq + 2 * jj;
        u64 pk = pack2(A[j0 * K + kk], A[j0 * K + K + kk]);
        sts_b64(abase + (unsigned)(i * 8), pk);
    }

    // --- t_mod partial reduce: 40 chunks per q-group, fully unrolled ---
    {
        float m = 0.0f;
        const float* gp = &g_partial[q * 40][b][k];
#pragma unroll
        for (int c = 0; c < 40; c++)
            m = fmaxf(m, gp[c * (B * K)]);
        pred[tid] = m;
    }

    // --- cell offset: top warp ---
    if (tid >= 992) {
        int lane = tid - 992;
        int ci = cell_idx[b];
        float v = cell_emb[ci * HID + lane] * W2[lane]
                + cell_emb[ci * HID + 32 + lane] * W2[32 + lane];
#pragma unroll
        for (int o = 16; o > 0; o >>= 1)
            v += __shfl_down_sync(0xffffffffu, v, o);
        if (lane == 0) g_coff[b] = v + b2[0];
    }
    __syncthreads();

    const float s_k = fmaxf(fmaxf(pred[k], pred[256 + k]),
                            fmaxf(pred[512 + k], pred[768 + k]));
    if (q == 0) Zs[k] = s_k;
    __syncthreads();

    // --- 10 APPNP steps, FFMA2 throughout ---
    const unsigned zA = zbase + (unsigned)(64 * q * 4);        // floats 64q..
    const unsigned zB = zA + 24 * 4;                            // floats 64q+24..
    const unsigned aTh = abase + (unsigned)(((q * 12) * 256 + k) * 8);

#pragma unroll 1
    for (int s = 0; s < STEPS; s++) {
        u64 acc = 0;
#pragma unroll
        for (int i = 0; i < 6; i++) {
            u64 z0, z1;
            lds_v2b64(zA + 16 * i, z0, z1);
            u64 a0 = lds_b64(aTh + (unsigned)((2 * i) * 256 * 8));
            u64 a1 = lds_b64(aTh + (unsigned)((2 * i + 1) * 256 * 8));
            ffma2(acc, a0, z0);
            ffma2(acc, a1, z1);
        }
#pragma unroll
        for (int i = 0; i < 10; i++) {
            u64 z0, z1;
            lds_v2b64(zB + 16 * i, z0, z1);
            ffma2(acc, regA2[2 * i], z0);
            ffma2(acc, regA2[2 * i + 1], z1);
        }
        float lo, hi;
        unpack2(acc, lo, hi);
        pred[tid] = lo + hi;
        __syncthreads();
        float v = (pred[k] + pred[256 + k]) + (pred[512 + k] + pred[768 + k]);
        float zn = fmaf(0.9f, v, 0.1f * s_k);
        if (q == 0) Zs[k] = zn;
        __syncthreads();
    }

    if (q == 0) g_Z[b][k] = Zs[k];
}

// ---------------------------------------------------------------------------
// K3: z_gene + MLP + out, 5 phases. 157 blocks x 1024 threads, 32 genes.
// B: (jh 0..7, p4 0..3, gl 0..31) -> float4-of-b partial dots (32 j each)
// C: 8-way j reduce -> zfin[16][32]
// D: (jh2 0..3, p 0..7, gl 0..31) -> partial MLP over 16 HID each
// E: 4-way y reduce + cell offset + store
// ---------------------------------------------------------------------------
#define K3_MS    0
#define K3_Z4    8224
#define K3_ZPART 12320
#define K3_WPACK 16416
#define K3_W2S   16672
#define K3_CTS   16736
#define K3_TTS   17248
#define K3_COFF  17760
#define K3_ZFIN  17776
#define K3_YPART 18288
#define K3_FLOATS 20336

__global__ __launch_bounds__(1024) void k3_out(
    const float* __restrict__ ctl,
    const float* __restrict__ t,
    const float* __restrict__ M,
    const float* __restrict__ W1,
    const float* __restrict__ b1,
    const float* __restrict__ W2,
    float* __restrict__ out)
{
    extern __shared__ float s3[];
    float*  Ms     = s3 + K3_MS;                  // [32][257]
    float4* Z4     = (float4*)(s3 + K3_Z4);       // [256][4] (b-quads)
    float4* zpart  = (float4*)(s3 + K3_ZPART);    // [8][4][32]
    float4* wpack  = (float4*)(s3 + K3_WPACK);    // [64] (w1c,w1t,w1z,b1)
    float*  W2s    = s3 + K3_W2S;                 // 64
    float*  cts    = s3 + K3_CTS;                 // [16][32]
    float*  tts    = s3 + K3_TTS;                 // [16][32]
    float*  coffs  = s3 + K3_COFF;                // 16
    float*  zfin   = s3 + K3_ZFIN;                // [16][32]
    float2* ypart  = (float2*)(s3 + K3_YPART);    // [4][256]

    const int tid = threadIdx.x;
    const int g0  = blockIdx.x * GT;

    // ---------- Phase A: stage ----------
    for (int i = tid; i < GT * 64; i += 1024) {
        int gl = i >> 6, jq = i & 63;
        int g = g0 + gl;
        float4 v = (g < G) ? *(const float4*)(M + (size_t)g * K + 4 * jq)
                           : make_float4(0.f, 0.f, 0.f, 0.f);
        float* d = Ms + gl * 257 + 4 * jq;
        d[0] = v.x; d[1] = v.y; d[2] = v.z; d[3] = v.w;
    }
    {
        int p4 = tid >> 8, j = tid & 255;
        float4 zz;
        zz.x = g_Z[4 * p4 + 0][j];
        zz.y = g_Z[4 * p4 + 1][j];
        zz.z = g_Z[4 * p4 + 2][j];
        zz.w = g_Z[4 * p4 + 3][j];
        Z4[j * 4 + p4] = zz;
    }
    if (tid < 64) {
        wpack[tid] = make_float4(W1[tid], W1[HID + tid], W1[2 * HID + tid], b1[tid]);
        W2s[tid]   = W2[tid];
    }
    if (tid < 512) {
        int bb = tid >> 5, gl = tid & 31;
        int g = g0 + gl;
        cts[tid] = (g < G) ? ctl[bb * G + g] : 0.0f;
        tts[tid] = (g < G) ? t[bb * G + g] : 0.0f;
    }
    if (tid < B) coffs[tid] = g_coff[tid];
    __syncthreads();

    // ---------- Phase B: partial z-dots (float4 of b) ----------
    {
        const int jh = tid >> 7;
        const int p4 = (tid >> 5) & 3;
        const int gl = tid & 31;
        const float* Mrow = Ms + gl * 257;
        float4 acc = make_float4(0.f, 0.f, 0.f, 0.f);
#pragma unroll
        for (int jj = 0; jj < 32; jj++) {
            int j = 32 * jh + jj;
            float  m = Mrow[j];                 // conflict-free (stride 257)
            float4 z = Z4[j * 4 + p4];          // broadcast
            acc.x = fmaf(m, z.x, acc.x);
            acc.y = fmaf(m, z.y, acc.y);
            acc.z = fmaf(m, z.z, acc.z);
            acc.w = fmaf(m, z.w, acc.w);
        }
        zpart[(jh * 4 + p4) * 32 + gl] = acc;
    }
    __syncthreads();

    // ---------- Phase C: reduce over 8 jh ----------
    if (tid < 128) {
        int p4 = tid >> 5, gl = tid & 31;
        float4 s = make_float4(0.f, 0.f, 0.f, 0.f);
#pragma unroll
        for (int jh = 0; jh < 8; jh++) {
            float4 v = zpart[(jh * 4 + p4) * 32 + gl];
            s.x += v.x; s.y += v.y; s.z += v.z; s.w += v.w;
        }
        zfin[(4 * p4 + 0) * 32 + gl] = s.x;
        zfin[(4 * p4 + 1) * 32 + gl] = s.y;
        zfin[(4 * p4 + 2) * 32 + gl] = s.z;
        zfin[(4 * p4 + 3) * 32 + gl] = s.w;
    }
    __syncthreads();

    // ---------- Phase D: partial MLP (16 HID each) ----------
    {
        const int jh2 = tid >> 8;
        const int r   = tid & 255;
        const int p   = r >> 5;
        const int gl  = r & 31;
        float z0 = zfin[p * 32 + gl],        z1 = zfin[(p + 8) * 32 + gl];
        float c0 = cts[p * 32 + gl],         c1 = cts[(p + 8) * 32 + gl];
        float t0 = tts[p * 32 + gl],         t1 = tts[(p + 8) * 32 + gl];
        float y0 = 0.f, y1 = 0.f;
#pragma unroll
        for (int jj = 0; jj < 16; jj++) {
            int j = 16 * jh2 + jj;
            float4 w = wpack[j];                // broadcast
            float  w2 = W2s[j];                 // broadcast
            float v0 = fmaf(c0, w.x, fmaf(t0, w.y, fmaf(z0, w.z, w.w)));
            float v1 = fmaf(c1, w.x, fmaf(t1, w.y, fmaf(z1, w.z, w.w)));
            y0 = fmaf(fmaxf(v0, 0.f), w2, y0);
            y1 = fmaf(fmaxf(v1, 0.f), w2, y1);
        }
        ypart[jh2 * 256 + r] = make_float2(y0, y1);
    }
    __syncthreads();

    // ---------- Phase E: reduce + store ----------
    if (tid < 256) {
        int p = tid >> 5, gl = tid & 31;
        int g = g0 + gl;
        if (g < G) {
            float2 a = ypart[tid],       bb = ypart[256 + tid];
            float2 c = ypart[512 + tid], d  = ypart[768 + tid];
            out[p * G + g]       = (a.x + bb.x) + (c.x + d.x) + coffs[p];
            out[(p + 8) * G + g] = (a.y + bb.y) + (c.y + d.y) + coffs[p + 8];
        }
    }
}
#define K3_SMEM (K3_FLOATS * (int)sizeof(float))

// ---------------------------------------------------------------------------
// metadata order: ctl, drug_targets, cell_idx, drug_fp, M, A, W1, b1,
//                 cell_emb, W2, b2   -> output [B, G] float32
// ---------------------------------------------------------------------------
extern "C" void kernel_launch(void* const* d_in, const int* in_sizes, int n_in,
                              void* d_out, int out_size)
{
    const float* ctl      = (const float*)d_in[0];
    const float* tgt      = (const float*)d_in[1];
    const int*   cell_idx = (const int*)  d_in[2];
    // d_in[3] = drug_fp (unused by the model)
    const float* M        = (const float*)d_in[4];
    const float* A        = (const float*)d_in[5];
    const float* W1       = (const float*)d_in[6];
    const float* b1       = (const float*)d_in[7];
    const float* cell_emb = (const float*)d_in[8];
    const float* W2       = (const float*)d_in[9];
    const float* b2       = (const float*)d_in[10];
    float* out = (float*)d_out;

    cudaFuncSetAttribute(k1_maxpool,
                         cudaFuncAttributeMaxDynamicSharedMemorySize, K1_SMEM);
    cudaFuncSetAttribute(k2_appnp,
                         cudaFuncAttributeMaxDynamicSharedMemorySize, K2_SMEM_BYTES);
    cudaFuncSetAttribute(k3_out,
                         cudaFuncAttributeMaxDynamicSharedMemorySize, K3_SMEM);

    k1_maxpool<<<NCHUNK, 1024, K1_SMEM>>>(tgt, M);
    k2_appnp<<<B, 1024, K2_SMEM_BYTES>>>(A, cell_idx, cell_emb, W2, b2);
    k3_out<<<(G + GT - 1) / GT, 1024, K3_SMEM>>>(ctl, tgt, M, W1, b1, W2, out);
}

// round 9
// speedup vs baseline: 1.8089x; 1.2769x over previous
#include <cuda_runtime.h>

#define B 16
#define G 5000
#define K 256
#define HID 64
#define STEPS 10
#define NCHUNK 148
#define NG1 34            // genes/block in K1 (148*34 = 5032 >= 5000)
#define NG1P 36           // padded gene slots
#define GT 40             // genes/block in K3 (125 blocks, all co-resident)

typedef unsigned long long u64;

// Scratch (no allocations allowed)
__device__ __align__(16) float g_partial[NCHUNK][B][K];  // 2.4 MB
__device__ __align__(16) float g_Z[B][K];
__device__ float g_coff[B];

// ---- packed fp32x2 helpers (FFMA2 is PTX-only) ----
__device__ __forceinline__ u64 pack2(float x, float y) {
    u64 r; asm("mov.b64 %0, {%1, %2};" : "=l"(r) : "f"(x), "f"(y)); return r;
}
__device__ __forceinline__ void unpack2(u64 v, float& x, float& y) {
    asm("mov.b64 {%0, %1}, %2;" : "=f"(x), "=f"(y) : "l"(v));
}
__device__ __forceinline__ void ffma2(u64& acc, u64 a, u64 b) {
    asm("fma.rn.f32x2 %0, %1, %2, %0;" : "+l"(acc) : "l"(a), "l"(b));
}
__device__ __forceinline__ u64 lds_b64(unsigned a) {
    u64 r; asm volatile("ld.shared.b64 %0, [%1];" : "=l"(r) : "r"(a)); return r;
}
__device__ __forceinline__ void lds_v2b64(unsigned a, u64& x, u64& y) {
    asm volatile("ld.shared.v2.b64 {%0, %1}, [%2];" : "=l"(x), "=l"(y) : "r"(a));
}
__device__ __forceinline__ void sts_b64(unsigned a, u64 v) {
    asm volatile("st.shared.b64 [%0], %1;" :: "r"(a), "l"(v) : "memory");
}
__device__ __forceinline__ void grid_dep_wait() {
    asm volatile("griddepcontrol.wait;" ::: "memory");
}

#define FMAXUPD(ACC, T, MV)                         \
    ACC.x = fmaxf(ACC.x, (T) * MV.x);               \
    ACC.y = fmaxf(ACC.y, (T) * MV.y);               \
    ACC.z = fmaxf(ACC.z, (T) * MV.z);               \
    ACC.w = fmaxf(ACC.w, (T) * MV.w);

// ---------------------------------------------------------------------------
// K1: max-pool. 148 blocks x 1024 threads — exactly 1 CTA/SM, no tail.
// Thread (q4 = tid&63, h, ge): 9 genes (ge+4u, u=0..8), two load groups 4+5.
// ---------------------------------------------------------------------------
__global__ __launch_bounds__(1024) void k1_maxpool(
    const float* __restrict__ t, const float* __restrict__ M)
{
    extern __shared__ float s1[];
    float*  ts   = s1;                    // [B][NG1P] = 576
    float4* red4 = (float4*)(s1 + 576);   // [64][64] float4 = 64 KB

    const int tid = threadIdx.x;
    const int g0  = blockIdx.x * NG1;

    for (int i = tid; i < B * NG1P; i += 1024) {
        int b = i / NG1P, gl = i % NG1P;
        int g = g0 + gl;
        ts[i] = (gl < NG1 && g < G) ? t[b * G + g] : 0.0f;
    }
    __syncthreads();

    const int q4 = tid & 63;
    const int h  = (tid >> 6) & 3;
    const int ge = tid >> 8;

    float4 acc[4];
#pragma unroll
    for (int ii = 0; ii < 4; ii++) acc[ii] = make_float4(0.f, 0.f, 0.f, 0.f);

    // group 1: u = 0..3
    {
        float4 mv[4];
#pragma unroll
        for (int u = 0; u < 4; u++) {
            int g = g0 + ge + 4 * u;
            mv[u] = (g < G) ? *(const float4*)(M + (size_t)g * K + 4 * q4)
                            : make_float4(0.f, 0.f, 0.f, 0.f);
        }
#pragma unroll
        for (int u = 0; u < 4; u++) {
            int gl = ge + 4 * u;
            float4 m = mv[u];
#pragma unroll
            for (int ii = 0; ii < 4; ii++) {
                float tv = ts[(4 * h + ii) * NG1P + gl];
                FMAXUPD(acc[ii], tv, m)
            }
        }
    }
    // group 2: u = 4..8
    {
        float4 mv[5];
#pragma unroll
        for (int v = 0; v < 5; v++) {
            int gl = ge + 4 * (4 + v);
            int g  = g0 + gl;
            mv[v] = (gl < NG1 && g < G)
                  ? *(const float4*)(M + (size_t)g * K + 4 * q4)
                  : make_float4(0.f, 0.f, 0.f, 0.f);
        }
#pragma unroll
        for (int v = 0; v < 5; v++) {
            int gl = ge + 4 * (4 + v);
            float4 m = mv[v];
#pragma unroll
            for (int ii = 0; ii < 4; ii++) {
                float tv = ts[(4 * h + ii) * NG1P + gl];
                FMAXUPD(acc[ii], tv, m)
            }
        }
    }

#pragma unroll
    for (int ii = 0; ii < 4; ii++)
        red4[(((ge * 4 + h) * 4 + ii) << 6) + q4] = acc[ii];
    __syncthreads();

    if (tid < 256) {
        int q4r = tid & 63, hr = tid >> 6;
#pragma unroll
        for (int ii = 0; ii < 4; ii++) {
            float4 a = red4[(((0 * 4 + hr) * 4 + ii) << 6) + q4r];
            float4 c = red4[(((1 * 4 + hr) * 4 + ii) << 6) + q4r];
            float4 d = red4[(((2 * 4 + hr) * 4 + ii) << 6) + q4r];
            float4 e = red4[(((3 * 4 + hr) * 4 + ii) << 6) + q4r];
            float4 r;
            r.x = fmaxf(fmaxf(a.x, c.x), fmaxf(d.x, e.x));
            r.y = fmaxf(fmaxf(a.y, c.y), fmaxf(d.y, e.y));
            r.z = fmaxf(fmaxf(a.z, c.z), fmaxf(d.z, e.z));
            r.w = fmaxf(fmaxf(a.w, c.w), fmaxf(d.w, e.w));
            *(float4*)(&g_partial[blockIdx.x][4 * hr + ii][4 * q4r]) = r;
        }
    }
}
#define K1_SMEM ((576 + 64 * 64 * 4) * (int)sizeof(float))

// ---------------------------------------------------------------------------
// K2: APPNP, packed fp32x2 FMA (R8 design). 16 blocks x 1024 threads.
// PDL: stages A (regs + smem) and cell offset BEFORE griddepcontrol.wait,
// then waits on K1 and reduces g_partial.
// ---------------------------------------------------------------------------
#define K2_ASM_BYTES (48 * 256 * 8)
#define K2_SMEM_BYTES (K2_ASM_BYTES + 1024 + 4096)

__global__ __launch_bounds__(1024, 1) void k2_appnp(
    const float* __restrict__ A,
    const int*   __restrict__ cell_idx,
    const float* __restrict__ cell_emb,
    const float* __restrict__ W2,
    const float* __restrict__ b2)
{
    extern __shared__ float sm[];
    float* Zs   = sm + K2_ASM_BYTES / 4;           // 256 floats
    float* pred = Zs + 256;                         // 1024 floats
    const unsigned abase = (unsigned)__cvta_generic_to_shared(sm);
    const unsigned zbase = abase + K2_ASM_BYTES;

    const int tid = threadIdx.x;
    const int b   = blockIdx.x;
    const int q   = tid >> 8;
    const int k   = tid & 255;

    // --- pre-wait: register A pairs, j in [64q+24, 64q+64) ---
    u64 regA2[20];
#pragma unroll
    for (int u = 0; u < 20; u++) {
        int j0 = 64 * q + 24 + 2 * u;
        regA2[u] = pack2(A[j0 * K + k], A[(j0 + 1) * K + k]);
    }

    // --- pre-wait: smem A pairs ---
    for (int i = tid; i < 48 * 256; i += 1024) {
        int r = i >> 8, kk = i & 255;
        int jq = r / 12, jj = r - 12 * jq;
        int j0 = 64 * jq + 2 * jj;
        u64 pk = pack2(A[j0 * K + kk], A[j0 * K + K + kk]);
        sts_b64(abase + (unsigned)(i * 8), pk);
    }

    // --- pre-wait: cell offset (independent of K1) ---
    if (tid >= 992) {
        int lane = tid - 992;
        int ci = cell_idx[b];
        float v = cell_emb[ci * HID + lane] * W2[lane]
                + cell_emb[ci * HID + 32 + lane] * W2[32 + lane];
#pragma unroll
        for (int o = 16; o > 0; o >>= 1)
            v += __shfl_down_sync(0xffffffffu, v, o);
        if (lane == 0) g_coff[b] = v + b2[0];
    }

    // --- wait for K1's g_partial ---
    grid_dep_wait();

    {
        float m = 0.0f;
        const float* gp = &g_partial[q * 37][b][k];
#pragma unroll
        for (int c = 0; c < 37; c++)
            m = fmaxf(m, gp[c * (B * K)]);
        pred[tid] = m;
    }
    __syncthreads();

    const float s_k = fmaxf(fmaxf(pred[k], pred[256 + k]),
                            fmaxf(pred[512 + k], pred[768 + k]));
    if (q == 0) Zs[k] = s_k;
    __syncthreads();

    const unsigned zA = zbase + (unsigned)(64 * q * 4);
    const unsigned zB = zA + 24 * 4;
    const unsigned aTh = abase + (unsigned)(((q * 12) * 256 + k) * 8);

#pragma unroll 1
    for (int s = 0; s < STEPS; s++) {
        u64 acc = 0;
#pragma unroll
        for (int i = 0; i < 6; i++) {
            u64 z0, z1;
            lds_v2b64(zA + 16 * i, z0, z1);
            u64 a0 = lds_b64(aTh + (unsigned)((2 * i) * 256 * 8));
            u64 a1 = lds_b64(aTh + (unsigned)((2 * i + 1) * 256 * 8));
            ffma2(acc, a0, z0);
            ffma2(acc, a1, z1);
        }
#pragma unroll
        for (int i = 0; i < 10; i++) {
            u64 z0, z1;
            lds_v2b64(zB + 16 * i, z0, z1);
            ffma2(acc, regA2[2 * i], z0);
            ffma2(acc, regA2[2 * i + 1], z1);
        }
        float lo, hi;
        unpack2(acc, lo, hi);
        pred[tid] = lo + hi;
        __syncthreads();
        float v = (pred[k] + pred[256 + k]) + (pred[512 + k] + pred[768 + k]);
        float zn = fmaf(0.9f, v, 0.1f * s_k);
        if (q == 0) Zs[k] = zn;
        __syncthreads();
    }

    if (q == 0) g_Z[b][k] = Zs[k];
}

// ---------------------------------------------------------------------------
// K3: z_gene + MLP + out. 125 blocks x 1024 threads, 40 genes/block.
// PDL: stages M/ctl/t/W BEFORE griddepcontrol.wait (overlaps K2 on idle SMs),
// then waits on K2 and runs the Z-dependent phases.
// Phase B: (jh 0..5, p4 0..3, gl 0..39) 960 workers, j-splits {43x4, 42x2}
// Phase C: 160 workers reduce 6 jh -> zfin[16][40]
// Phase D: (jh2 0..1, p 0..7, gl 0..39) 640 workers, 32 HID each
// Phase E: 320 workers: 2-way reduce + coffs + store
// ---------------------------------------------------------------------------
#define K3_MS     0
#define K3_Z4     10280
#define K3_ZPART  14376
#define K3_WPACK  18216
#define K3_W2S    18472
#define K3_CTS    18536
#define K3_TTS    19176
#define K3_COFF   19816
#define K3_ZFIN   19832
#define K3_YPART  20472
#define K3_FLOATS 21752

__global__ __launch_bounds__(1024) void k3_out(
    const float* __restrict__ ctl,
    const float* __restrict__ t,
    const float* __restrict__ M,
    const float* __restrict__ W1,
    const float* __restrict__ b1,
    const float* __restrict__ W2,
    float* __restrict__ out)
{
    extern __shared__ float s3[];
    float*  Ms     = s3 + K3_MS;                  // [40][257]
    float4* Z4     = (float4*)(s3 + K3_Z4);       // [256][4]
    float4* zpart  = (float4*)(s3 + K3_ZPART);    // [6][4][40]
    float4* wpack  = (float4*)(s3 + K3_WPACK);    // [64]
    float*  W2s    = s3 + K3_W2S;                 // 64
    float*  cts    = s3 + K3_CTS;                 // [16][40]
    float*  tts    = s3 + K3_TTS;                 // [16][40]
    float*  coffs  = s3 + K3_COFF;                // 16
    float*  zfin   = s3 + K3_ZFIN;                // [16][40]
    float2* ypart  = (float2*)(s3 + K3_YPART);    // [2][320]

    const int tid = threadIdx.x;
    const int g0  = blockIdx.x * GT;

    // ---------- pre-wait staging (independent of K2) ----------
    for (int i = tid; i < GT * 64; i += 1024) {
        int gl = i >> 6, jq = i & 63;
        int g = g0 + gl;
        float4 v = (g < G) ? *(const float4*)(M + (size_t)g * K + 4 * jq)
                           : make_float4(0.f, 0.f, 0.f, 0.f);
        float* d = Ms + gl * 257 + 4 * jq;
        d[0] = v.x; d[1] = v.y; d[2] = v.z; d[3] = v.w;
    }
    if (tid < 64) {
        wpack[tid] = make_float4(W1[tid], W1[HID + tid], W1[2 * HID + tid], b1[tid]);
        W2s[tid]   = W2[tid];
    }
    if (tid < B * GT) {
        int bb = tid / GT, gl = tid % GT;
        int g = g0 + gl;
        cts[tid] = (g < G) ? ctl[bb * G + g] : 0.0f;
        tts[tid] = (g < G) ? t[bb * G + g] : 0.0f;
    }

    // ---------- wait for K2's g_Z / g_coff ----------
    grid_dep_wait();

    {
        int p4 = tid >> 8, j = tid & 255;
        float4 zz;
        zz.x = g_Z[4 * p4 + 0][j];
        zz.y = g_Z[4 * p4 + 1][j];
        zz.z = g_Z[4 * p4 + 2][j];
        zz.w = g_Z[4 * p4 + 3][j];
        Z4[j * 4 + p4] = zz;
    }
    if (tid < B) coffs[tid] = g_coff[tid];
    __syncthreads();

    // ---------- Phase B: partial z-dots ----------
    if (tid < 960) {
        const int jh = tid / 160;
        const int r  = tid - jh * 160;
        const int p4 = r / 40;
        const int gl = r - p4 * 40;
        const int j0 = (jh <= 4) ? jh * 43 : 214;
        const int j1 = (jh <= 3) ? j0 + 43 : j0 + 42;
        const float* Mrow = Ms + gl * 257;
        float4 acc = make_float4(0.f, 0.f, 0.f, 0.f);
        for (int j = j0; j < j1; j++) {
            float  m = Mrow[j];
            float4 z = Z4[j * 4 + p4];
            acc.x = fmaf(m, z.x, acc.x);
            acc.y = fmaf(m, z.y, acc.y);
            acc.z = fmaf(m, z.z, acc.z);
            acc.w = fmaf(m, z.w, acc.w);
        }
        zpart[(jh * 4 + p4) * 40 + gl] = acc;
    }
    __syncthreads();

    // ---------- Phase C: reduce over 6 jh ----------
    if (tid < 160) {
        int p4 = tid / 40, gl = tid - p4 * 40;
        float4 s = make_float4(0.f, 0.f, 0.f, 0.f);
#pragma unroll
        for (int jh = 0; jh < 6; jh++) {
            float4 v = zpart[(jh * 4 + p4) * 40 + gl];
            s.x += v.x; s.y += v.y; s.z += v.z; s.w += v.w;
        }
        zfin[(4 * p4 + 0) * 40 + gl] = s.x;
        zfin[(4 * p4 + 1) * 40 + gl] = s.y;
        zfin[(4 * p4 + 2) * 40 + gl] = s.z;
        zfin[(4 * p4 + 3) * 40 + gl] = s.w;
    }
    __syncthreads();

    // ---------- Phase D: partial MLP (32 HID each) ----------
    if (tid < 640) {
        const int jh2 = tid / 320;
        const int r   = tid - jh2 * 320;
        const int p   = r / 40;
        const int gl  = r - p * 40;
        float z0 = zfin[p * 40 + gl],  z1 = zfin[(p + 8) * 40 + gl];
        float c0 = cts[p * 40 + gl],   c1 = cts[(p + 8) * 40 + gl];
        float t0 = tts[p * 40 + gl],   t1 = tts[(p + 8) * 40 + gl];
        float y0 = 0.f, y1 = 0.f;
#pragma unroll
        for (int jj = 0; jj < 32; jj++) {
            int j = 32 * jh2 + jj;
            float4 w = wpack[j];
            float  w2 = W2s[j];
            float v0 = fmaf(c0, w.x, fmaf(t0, w.y, fmaf(z0, w.z, w.w)));
            float v1 = fmaf(c1, w.x, fmaf(t1, w.y, fmaf(z1, w.z, w.w)));
            y0 = fmaf(fmaxf(v0, 0.f), w2, y0);
            y1 = fmaf(fmaxf(v1, 0.f), w2, y1);
        }
        ypart[jh2 * 320 + r] = make_float2(y0, y1);
    }
    __syncthreads();

    // ---------- Phase E: reduce + store ----------
    if (tid < 320) {
        int p = tid / 40, gl = tid - p * 40;
        int g = g0 + gl;
        if (g < G) {
            float2 a = ypart[tid], bb = ypart[320 + tid];
            out[p * G + g]       = (a.x + bb.x) + coffs[p];
            out[(p + 8) * G + g] = (a.y + bb.y) + coffs[p + 8];
        }
    }
}
#define K3_SMEM (K3_FLOATS * (int)sizeof(float))

// ---------------------------------------------------------------------------
// metadata order: ctl, drug_targets, cell_idx, drug_fp, M, A, W1, b1,
//                 cell_emb, W2, b2   -> output [B, G] float32
// ---------------------------------------------------------------------------
extern "C" void kernel_launch(void* const* d_in, const int* in_sizes, int n_in,
                              void* d_out, int out_size)
{
    const float* ctl      = (const float*)d_in[0];
    const float* tgt      = (const float*)d_in[1];
    const int*   cell_idx = (const int*)  d_in[2];
    // d_in[3] = drug_fp (unused by the model)
    const float* M        = (const float*)d_in[4];
    const float* A        = (const float*)d_in[5];
    const float* W1       = (const float*)d_in[6];
    const float* b1       = (const float*)d_in[7];
    const float* cell_emb = (const float*)d_in[8];
    const float* W2       = (const float*)d_in[9];
    const float* b2       = (const float*)d_in[10];
    float* out = (float*)d_out;

    cudaFuncSetAttribute(k1_maxpool,
                         cudaFuncAttributeMaxDynamicSharedMemorySize, K1_SMEM);
    cudaFuncSetAttribute(k2_appnp,
                         cudaFuncAttributeMaxDynamicSharedMemorySize, K2_SMEM_BYTES);
    cudaFuncSetAttribute(k3_out,
                         cudaFuncAttributeMaxDynamicSharedMemorySize, K3_SMEM);

    k1_maxpool<<<NCHUNK, 1024, K1_SMEM>>>(tgt, M);

    cudaLaunchAttribute pdl[1];
    pdl[0].id = cudaLaunchAttributeProgrammaticStreamSerialization;
    pdl[0].val.programmaticStreamSerializationAllowed = 1;

    {
        cudaLaunchConfig_t cfg = {};
        cfg.gridDim = dim3(B, 1, 1);
        cfg.blockDim = dim3(1024, 1, 1);
        cfg.dynamicSmemBytes = K2_SMEM_BYTES;
        cfg.attrs = pdl;
        cfg.numAttrs = 1;
        cudaLaunchKernelEx(&cfg, k2_appnp, A, cell_idx, cell_emb, W2, b2);
    }
    {
        cudaLaunchConfig_t cfg = {};
        cfg.gridDim = dim3((G + GT - 1) / GT, 1, 1);   // 125
        cfg.blockDim = dim3(1024, 1, 1);
        cfg.dynamicSmemBytes = K3_SMEM;
        cfg.attrs = pdl;
        cfg.numAttrs = 1;
        cudaLaunchKernelEx(&cfg, k3_out, ctl, tgt, M, W1, b1, W2, out);
    }
}

// round 10
// speedup vs baseline: 1.8308x; 1.0121x over previous
#include <cuda_runtime.h>

#define B 16
#define G 5000
#define K 256
#define HID 64
#define STEPS 10
#define NCHUNK 148
#define NG1 34            // genes/block in K1 (148*34 = 5032 >= 5000)
#define NG1P 36           // padded gene slots
#define GT 40             // genes/block in K3 (125 blocks)

typedef unsigned long long u64;

// Scratch (no allocations allowed)
__device__ __align__(16) float g_partial[NCHUNK][B][K];  // 2.4 MB
__device__ __align__(16) float g_Z[B][K];
__device__ float g_coff[B];

// ---- packed fp32x2 helpers (FFMA2 is PTX-only) ----
__device__ __forceinline__ u64 pack2(float x, float y) {
    u64 r; asm("mov.b64 %0, {%1, %2};" : "=l"(r) : "f"(x), "f"(y)); return r;
}
__device__ __forceinline__ void unpack2(u64 v, float& x, float& y) {
    asm("mov.b64 {%0, %1}, %2;" : "=f"(x), "=f"(y) : "l"(v));
}
__device__ __forceinline__ void ffma2(u64& acc, u64 a, u64 b) {
    asm("fma.rn.f32x2 %0, %1, %2, %0;" : "+l"(acc) : "l"(a), "l"(b));
}
__device__ __forceinline__ u64 lds_b64(unsigned a) {
    u64 r; asm volatile("ld.shared.b64 %0, [%1];" : "=l"(r) : "r"(a)); return r;
}
__device__ __forceinline__ void lds_v2b64(unsigned a, u64& x, u64& y) {
    asm volatile("ld.shared.v2.b64 {%0, %1}, [%2];" : "=l"(x), "=l"(y) : "r"(a));
}
__device__ __forceinline__ void sts_b64(unsigned a, u64 v) {
    asm volatile("st.shared.b64 [%0], %1;" :: "r"(a), "l"(v) : "memory");
}
__device__ __forceinline__ void grid_dep_wait() {
    asm volatile("griddepcontrol.wait;" ::: "memory");
}

#define FMAXUPD(ACC, T, MV)                         \
    ACC.x = fmaxf(ACC.x, (T) * MV.x);               \
    ACC.y = fmaxf(ACC.y, (T) * MV.y);               \
    ACC.z = fmaxf(ACC.z, (T) * MV.z);               \
    ACC.w = fmaxf(ACC.w, (T) * MV.w);

// ---------------------------------------------------------------------------
// K1: max-pool. 148 blocks x 1024 threads, 1 CTA/SM.
// M tile staged once into smem (no 4x duplicated LDG, no WAR windows),
// compute reads via LDS.128. Thread (q4, h, ge): b-quad h, k-quad q4,
// genes ge+4u (u=0..8). Products >= 0 so init 0 is exact.
// ---------------------------------------------------------------------------
__global__ __launch_bounds__(1024) void k1_maxpool(
    const float* __restrict__ t, const float* __restrict__ M)
{
    extern __shared__ float s1[];
    float*  ts   = s1;                         // [B][NG1P] = 576
    float*  Ms   = s1 + 576;                   // [NG1P][256] = 9216
    float4* red4 = (float4*)(s1 + 576 + 9216); // [64][64] float4 = 64 KB

    const int tid = threadIdx.x;
    const int g0  = blockIdx.x * NG1;

    for (int i = tid; i < B * NG1P; i += 1024) {
        int b = i / NG1P, gl = i % NG1P;
        int g = g0 + gl;
        ts[i] = (gl < NG1 && g < G) ? t[b * G + g] : 0.0f;
    }
    for (int i = tid; i < NG1P * 64; i += 1024) {
        int gl = i >> 6, jq = i & 63;
        int g = g0 + gl;
        float4 v = (gl < NG1 && g < G)
                 ? *(const float4*)(M + (size_t)g * K + 4 * jq)
                 : make_float4(0.f, 0.f, 0.f, 0.f);
        *(float4*)(Ms + gl * 256 + 4 * jq) = v;
    }
    __syncthreads();

    const int q4 = tid & 63;
    const int h  = (tid >> 6) & 3;
    const int ge = tid >> 8;

    float4 acc[4];
#pragma unroll
    for (int ii = 0; ii < 4; ii++) acc[ii] = make_float4(0.f, 0.f, 0.f, 0.f);

#pragma unroll
    for (int u = 0; u < 9; u++) {
        const int gl = ge + 4 * u;                 // < 36
        float4 m = *(const float4*)(Ms + gl * 256 + 4 * q4);
#pragma unroll
        for (int ii = 0; ii < 4; ii++) {
            float tv = ts[(4 * h + ii) * NG1P + gl];
            FMAXUPD(acc[ii], tv, m)
        }
    }

#pragma unroll
    for (int ii = 0; ii < 4; ii++)
        red4[(((ge * 4 + h) * 4 + ii) << 6) + q4] = acc[ii];
    __syncthreads();

    if (tid < 256) {
        int q4r = tid & 63, hr = tid >> 6;
#pragma unroll
        for (int ii = 0; ii < 4; ii++) {
            float4 a = red4[(((0 * 4 + hr) * 4 + ii) << 6) + q4r];
            float4 c = red4[(((1 * 4 + hr) * 4 + ii) << 6) + q4r];
            float4 d = red4[(((2 * 4 + hr) * 4 + ii) << 6) + q4r];
            float4 e = red4[(((3 * 4 + hr) * 4 + ii) << 6) + q4r];
            float4 r;
            r.x = fmaxf(fmaxf(a.x, c.x), fmaxf(d.x, e.x));
            r.y = fmaxf(fmaxf(a.y, c.y), fmaxf(d.y, e.y));
            r.z = fmaxf(fmaxf(a.z, c.z), fmaxf(d.z, e.z));
            r.w = fmaxf(fmaxf(a.w, c.w), fmaxf(d.w, e.w));
            *(float4*)(&g_partial[blockIdx.x][4 * hr + ii][4 * q4r]) = r;
        }
    }
}
#define K1_SMEM ((576 + 9216 + 64 * 64 * 4) * (int)sizeof(float))

// ---------------------------------------------------------------------------
// K2: APPNP, packed fp32x2 FMA. 16 blocks x 1024 threads.
// Thread (q, k) owns j in [64q, 64q+64) as 32 pairs: 10 in smem, 22 in regs.
// PDL: stages A + cell offset before griddepcontrol.wait.
// ---------------------------------------------------------------------------
#define K2_ASM_BYTES (40 * 256 * 8)
#define K2_SMEM_BYTES (K2_ASM_BYTES + 1024 + 4096)

__global__ __launch_bounds__(1024, 1) void k2_appnp(
    const float* __restrict__ A,
    const int*   __restrict__ cell_idx,
    const float* __restrict__ cell_emb,
    const float* __restrict__ W2,
    const float* __restrict__ b2)
{
    extern __shared__ float sm[];
    float* Zs   = sm + K2_ASM_BYTES / 4;           // 256 floats
    float* pred = Zs + 256;                         // 1024 floats
    const unsigned abase = (unsigned)__cvta_generic_to_shared(sm);
    const unsigned zbase = abase + K2_ASM_BYTES;

    const int tid = threadIdx.x;
    const int b   = blockIdx.x;
    const int q   = tid >> 8;
    const int k   = tid & 255;

    // --- pre-wait: register A pairs, j in [64q+20, 64q+64) ---
    u64 regA2[22];
#pragma unroll
    for (int u = 0; u < 22; u++) {
        int j0 = 64 * q + 20 + 2 * u;
        regA2[u] = pack2(A[j0 * K + k], A[(j0 + 1) * K + k]);
    }

    // --- pre-wait: smem A pairs: rows r = q*10 + jj, j = 64q + 2jj ---
    for (int i = tid; i < 40 * 256; i += 1024) {
        int r = i >> 8, kk = i & 255;
        int jq = r / 10, jj = r - 10 * jq;
        int j0 = 64 * jq + 2 * jj;
        u64 pk = pack2(A[j0 * K + kk], A[j0 * K + K + kk]);
        sts_b64(abase + (unsigned)(i * 8), pk);
    }

    // --- pre-wait: cell offset ---
    if (tid >= 992) {
        int lane = tid - 992;
        int ci = cell_idx[b];
        float v = cell_emb[ci * HID + lane] * W2[lane]
                + cell_emb[ci * HID + 32 + lane] * W2[32 + lane];
#pragma unroll
        for (int o = 16; o > 0; o >>= 1)
            v += __shfl_down_sync(0xffffffffu, v, o);
        if (lane == 0) g_coff[b] = v + b2[0];
    }

    grid_dep_wait();

    {
        float m = 0.0f;
        const float* gp = &g_partial[q * 37][b][k];
#pragma unroll
        for (int c = 0; c < 37; c++)
            m = fmaxf(m, gp[c * (B * K)]);
        pred[tid] = m;
    }
    __syncthreads();

    const float s_k = fmaxf(fmaxf(pred[k], pred[256 + k]),
                            fmaxf(pred[512 + k], pred[768 + k]));
    if (q == 0) Zs[k] = s_k;
    __syncthreads();

    const unsigned zA = zbase + (unsigned)(64 * q * 4);     // j = 64q..
    const unsigned zB = zA + 20 * 4;                         // j = 64q+20..
    const unsigned aTh = abase + (unsigned)(((q * 10) * 256 + k) * 8);

#pragma unroll 1
    for (int s = 0; s < STEPS; s++) {
        u64 acc = 0;
#pragma unroll
        for (int i = 0; i < 5; i++) {
            u64 z0, z1;
            lds_v2b64(zA + 16 * i, z0, z1);
            u64 a0 = lds_b64(aTh + (unsigned)((2 * i) * 256 * 8));
            u64 a1 = lds_b64(aTh + (unsigned)((2 * i + 1) * 256 * 8));
            ffma2(acc, a0, z0);
            ffma2(acc, a1, z1);
        }
#pragma unroll
        for (int i = 0; i < 11; i++) {
            u64 z0, z1;
            lds_v2b64(zB + 16 * i, z0, z1);
            ffma2(acc, regA2[2 * i], z0);
            ffma2(acc, regA2[2 * i + 1], z1);
        }
        float lo, hi;
        unpack2(acc, lo, hi);
        pred[tid] = lo + hi;
        __syncthreads();
        float v = (pred[k] + pred[256 + k]) + (pred[512 + k] + pred[768 + k]);
        float zn = fmaf(0.9f, v, 0.1f * s_k);
        if (q == 0) Zs[k] = zn;
        __syncthreads();
    }

    if (q == 0) g_Z[b][k] = Zs[k];
}

// ---------------------------------------------------------------------------
// K3: z_gene + MLP + out. 125 blocks x 1024 threads, 40 genes/block.
// PDL: stages M/ctl/t/W before griddepcontrol.wait.
// ---------------------------------------------------------------------------
#define K3_MS     0
#define K3_Z4     10280
#define K3_ZPART  14376
#define K3_WPACK  18216
#define K3_W2S    18472
#define K3_CTS    18536
#define K3_TTS    19176
#define K3_COFF   19816
#define K3_ZFIN   19832
#define K3_YPART  20472
#define K3_FLOATS 21752

__global__ __launch_bounds__(1024) void k3_out(
    const float* __restrict__ ctl,
    const float* __restrict__ t,
    const float* __restrict__ M,
    const float* __restrict__ W1,
    const float* __restrict__ b1,
    const float* __restrict__ W2,
    float* __restrict__ out)
{
    extern __shared__ float s3[];
    float*  Ms     = s3 + K3_MS;                  // [40][257]
    float4* Z4     = (float4*)(s3 + K3_Z4);       // [256][4]
    float4* zpart  = (float4*)(s3 + K3_ZPART);    // [6][4][40]
    float4* wpack  = (float4*)(s3 + K3_WPACK);    // [64]
    float*  W2s    = s3 + K3_W2S;                 // 64
    float*  cts    = s3 + K3_CTS;                 // [16][40]
    float*  tts    = s3 + K3_TTS;                 // [16][40]
    float*  coffs  = s3 + K3_COFF;                // 16
    float*  zfin   = s3 + K3_ZFIN;                // [16][40]
    float2* ypart  = (float2*)(s3 + K3_YPART);    // [2][320]

    const int tid = threadIdx.x;
    const int g0  = blockIdx.x * GT;

    // ---------- pre-wait staging ----------
    for (int i = tid; i < GT * 64; i += 1024) {
        int gl = i >> 6, jq = i & 63;
        int g = g0 + gl;
        float4 v = (g < G) ? *(const float4*)(M + (size_t)g * K + 4 * jq)
                           : make_float4(0.f, 0.f, 0.f, 0.f);
        float* d = Ms + gl * 257 + 4 * jq;
        d[0] = v.x; d[1] = v.y; d[2] = v.z; d[3] = v.w;
    }
    if (tid < 64) {
        wpack[tid] = make_float4(W1[tid], W1[HID + tid], W1[2 * HID + tid], b1[tid]);
        W2s[tid]   = W2[tid];
    }
    if (tid < B * GT) {
        int bb = tid / GT, gl = tid % GT;
        int g = g0 + gl;
        cts[tid] = (g < G) ? ctl[bb * G + g] : 0.0f;
        tts[tid] = (g < G) ? t[bb * G + g] : 0.0f;
    }

    grid_dep_wait();

    {
        int p4 = tid >> 8, j = tid & 255;
        float4 zz;
        zz.x = g_Z[4 * p4 + 0][j];
        zz.y = g_Z[4 * p4 + 1][j];
        zz.z = g_Z[4 * p4 + 2][j];
        zz.w = g_Z[4 * p4 + 3][j];
        Z4[j * 4 + p4] = zz;
    }
    if (tid < B) coffs[tid] = g_coff[tid];
    __syncthreads();

    // ---------- Phase B: partial z-dots ----------
    if (tid < 960) {
        const int jh = tid / 160;
        const int r  = tid - jh * 160;
        const int p4 = r / 40;
        const int gl = r - p4 * 40;
        const int j0 = (jh <= 4) ? jh * 43 : 214;
        const int j1 = (jh <= 3) ? j0 + 43 : j0 + 42;
        const float* Mrow = Ms + gl * 257;
        float4 acc = make_float4(0.f, 0.f, 0.f, 0.f);
        for (int j = j0; j < j1; j++) {
            float  m = Mrow[j];
            float4 z = Z4[j * 4 + p4];
            acc.x = fmaf(m, z.x, acc.x);
            acc.y = fmaf(m, z.y, acc.y);
            acc.z = fmaf(m, z.z, acc.z);
            acc.w = fmaf(m, z.w, acc.w);
        }
        zpart[(jh * 4 + p4) * 40 + gl] = acc;
    }
    __syncthreads();

    // ---------- Phase C: reduce over 6 jh ----------
    if (tid < 160) {
        int p4 = tid / 40, gl = tid - p4 * 40;
        float4 s = make_float4(0.f, 0.f, 0.f, 0.f);
#pragma unroll
        for (int jh = 0; jh < 6; jh++) {
            float4 v = zpart[(jh * 4 + p4) * 40 + gl];
            s.x += v.x; s.y += v.y; s.z += v.z; s.w += v.w;
        }
        zfin[(4 * p4 + 0) * 40 + gl] = s.x;
        zfin[(4 * p4 + 1) * 40 + gl] = s.y;
        zfin[(4 * p4 + 2) * 40 + gl] = s.z;
        zfin[(4 * p4 + 3) * 40 + gl] = s.w;
    }
    __syncthreads();

    // ---------- Phase D: partial MLP (32 HID each) ----------
    if (tid < 640) {
        const int jh2 = tid / 320;
        const int r   = tid - jh2 * 320;
        const int p   = r / 40;
        const int gl  = r - p * 40;
        float z0 = zfin[p * 40 + gl],  z1 = zfin[(p + 8) * 40 + gl];
        float c0 = cts[p * 40 + gl],   c1 = cts[(p + 8) * 40 + gl];
        float t0 = tts[p * 40 + gl],   t1 = tts[(p + 8) * 40 + gl];
        float y0 = 0.f, y1 = 0.f;
#pragma unroll
        for (int jj = 0; jj < 32; jj++) {
            int j = 32 * jh2 + jj;
            float4 w = wpack[j];
            float  w2 = W2s[j];
            float v0 = fmaf(c0, w.x, fmaf(t0, w.y, fmaf(z0, w.z, w.w)));
            float v1 = fmaf(c1, w.x, fmaf(t1, w.y, fmaf(z1, w.z, w.w)));
            y0 = fmaf(fmaxf(v0, 0.f), w2, y0);
            y1 = fmaf(fmaxf(v1, 0.f), w2, y1);
        }
        ypart[jh2 * 320 + r] = make_float2(y0, y1);
    }
    __syncthreads();

    // ---------- Phase E: reduce + store ----------
    if (tid < 320) {
        int p = tid / 40, gl = tid - p * 40;
        int g = g0 + gl;
        if (g < G) {
            float2 a = ypart[tid], bb = ypart[320 + tid];
            out[p * G + g]       = (a.x + bb.x) + coffs[p];
            out[(p + 8) * G + g] = (a.y + bb.y) + coffs[p + 8];
        }
    }
}
#define K3_SMEM (K3_FLOATS * (int)sizeof(float))

// ---------------------------------------------------------------------------
// metadata order: ctl, drug_targets, cell_idx, drug_fp, M, A, W1, b1,
//                 cell_emb, W2, b2   -> output [B, G] float32
// ---------------------------------------------------------------------------
extern "C" void kernel_launch(void* const* d_in, const int* in_sizes, int n_in,
                              void* d_out, int out_size)
{
    const float* ctl      = (const float*)d_in[0];
    const float* tgt      = (const float*)d_in[1];
    const int*   cell_idx = (const int*)  d_in[2];
    // d_in[3] = drug_fp (unused by the model)
    const float* M        = (const float*)d_in[4];
    const float* A        = (const float*)d_in[5];
    const float* W1       = (const float*)d_in[6];
    const float* b1       = (const float*)d_in[7];
    const float* cell_emb = (const float*)d_in[8];
    const float* W2       = (const float*)d_in[9];
    const float* b2       = (const float*)d_in[10];
    float* out = (float*)d_out;

    cudaFuncSetAttribute(k1_maxpool,
                         cudaFuncAttributeMaxDynamicSharedMemorySize, K1_SMEM);
    cudaFuncSetAttribute(k2_appnp,
                         cudaFuncAttributeMaxDynamicSharedMemorySize, K2_SMEM_BYTES);
    cudaFuncSetAttribute(k3_out,
                         cudaFuncAttributeMaxDynamicSharedMemorySize, K3_SMEM);

    k1_maxpool<<<NCHUNK, 1024, K1_SMEM>>>(tgt, M);

    cudaLaunchAttribute pdl[1];
    pdl[0].id = cudaLaunchAttributeProgrammaticStreamSerialization;
    pdl[0].val.programmaticStreamSerializationAllowed = 1;

    {
        cudaLaunchConfig_t cfg = {};
        cfg.gridDim = dim3(B, 1, 1);
        cfg.blockDim = dim3(1024, 1, 1);
        cfg.dynamicSmemBytes = K2_SMEM_BYTES;
        cfg.attrs = pdl;
        cfg.numAttrs = 1;
        cudaLaunchKernelEx(&cfg, k2_appnp, A, cell_idx, cell_emb, W2, b2);
    }
    {
        cudaLaunchConfig_t cfg = {};
        cfg.gridDim = dim3((G + GT - 1) / GT, 1, 1);   // 125
        cfg.blockDim = dim3(1024, 1, 1);
        cfg.dynamicSmemBytes = K3_SMEM;
        cfg.attrs = pdl;
        cfg.numAttrs = 1;
        cudaLaunchKernelEx(&cfg, k3_out, ctl, tgt, M, W1, b1, W2, out);
    }
}